// round 5
// baseline (speedup 1.0000x reference)
#include <cuda_runtime.h>

#define N_MAX     1048576
#define SEGS      (64 * 4096)   // 262144 segments
#define GRID_DIM  64
#define NUM_CELLS 4096
#define SCAN_BLOCKS 256

// ---- scratch (static device globals; zero-initialized at module load) ----
__device__ int g_idx[N_MAX];          // per-point cell index
__device__ int g_pids[N_MAX];         // point ids sorted by cell
__device__ int g_counts[SEGS];        // points per cell (zeroed by k_scan for next call)
__device__ int g_offsets[SEGS];       // exclusive prefix of counts
__device__ int g_cursor[SEGS];        // running write cursor for scatter
__device__ int g_prefix[SCAN_BLOCKS]; // lookback inclusive prefixes
__device__ volatile int g_flag[SCAN_BLOCKS]; // lookback ready flags (reset by k_gather)

// count for cell i = cursor[i] - offsets[i]: g_counts was re-zeroed by k_scan,
// but k_scatter advanced cursor by exactly the cell count.
__device__ __forceinline__ int cell_count(int i) {
    return g_cursor[i] - g_offsets[i];
}

// ---------------------------------------------------------------
// pos/batch are int32 (JAX x64 disabled => int64 request materializes int32)
__global__ void k_hist(const int2* __restrict__ pos,
                       const int* __restrict__ batch, int n) {
    int i = blockIdx.x * blockDim.x + threadIdx.x;
    if (i >= n) return;
    int2 p = pos[i];
    int idx = batch[i] * NUM_CELLS
            + (p.x >> 2) * GRID_DIM
            + (p.y >> 2);
    g_idx[i] = idx;
    atomicAdd(&g_counts[idx], 1);
}

// single-pass exclusive scan over SEGS counts via decoupled lookback.
// Also: re-zeros g_counts (for the next graph replay) and initializes g_cursor.
__global__ void k_scan() {
    int bid  = blockIdx.x;
    int i    = bid * 1024 + threadIdx.x;
    int lane = threadIdx.x & 31;
    int wid  = threadIdx.x >> 5;

    int v = g_counts[i];
    g_counts[i] = 0;                       // consumed; reset for next replay

    int incl = v;
    #pragma unroll
    for (int d = 1; d < 32; d <<= 1) {
        int u = __shfl_up_sync(0xffffffffu, incl, d);
        if (lane >= d) incl += u;
    }
    __shared__ int ws[32];
    __shared__ int wexcl[32];
    __shared__ int base_s;
    if (lane == 31) ws[wid] = incl;
    __syncthreads();
    if (wid == 0) {
        int w  = ws[lane];
        int wi = w;
        #pragma unroll
        for (int d = 1; d < 32; d <<= 1) {
            int u = __shfl_up_sync(0xffffffffu, wi, d);
            if (lane >= d) wi += u;
        }
        wexcl[lane] = wi - w;
        if (lane == 31) {
            int total = wi;                // block total
            int base  = 0;
            if (bid > 0) {
                while (g_flag[bid - 1] == 0) { __nanosleep(40); }
                __threadfence();
                base = g_prefix[bid - 1];
            }
            g_prefix[bid] = base + total;
            __threadfence();
            g_flag[bid] = 1;
            base_s = base;
        }
    }
    __syncthreads();
    int o = incl - v + wexcl[wid] + base_s;
    g_offsets[i] = o;
    g_cursor[i]  = o;
}

__global__ void k_scatter(int n) {
    int i = blockIdx.x * blockDim.x + threadIdx.x;
    if (i >= n) return;
    int idx = g_idx[i];
    int p = atomicAdd(&g_cursor[idx], 1);
    g_pids[p] = i;
}

// one warp per cell. Lanes 0-15 process even points, lanes 16-31 odd points,
// each lane holding 4 channels (float4). Groups combined via shfl_xor(16).
// Block 0 additionally resets the lookback flags for the next replay.
__global__ void k_gather(const float4* __restrict__ x4, float4* __restrict__ out4) {
    if (blockIdx.x == 0 && threadIdx.x < SCAN_BLOCKS)
        g_flag[threadIdx.x] = 0;

    int warp = (blockIdx.x * blockDim.x + threadIdx.x) >> 5;
    int lane = threadIdx.x & 31;
    if (warp >= SEGS) return;

    int count = cell_count(warp);
    int start = g_offsets[warp];
    int g = lane >> 4;          // point-pair group
    int s = lane & 15;          // float4 column within row

    float4 acc = make_float4(0.f, 0.f, 0.f, 0.f);
    if (count > 0) {
        const float ninf = __int_as_float(0xff800000);
        acc = make_float4(ninf, ninf, ninf, ninf);

        int c0 = count < 32 ? count : 32;
        int mypid = (lane < c0) ? g_pids[start + lane] : 0;
        for (int j = 0; j < c0; j += 2) {
            int jj = j + g; if (jj >= c0) jj = c0 - 1;    // odd tail: dup last
            int pid = __shfl_sync(0xffffffffu, mypid, jj);
            float4 v = x4[pid * 16 + s];                  // 256B row, 2 points/iter
            acc.x = fmaxf(acc.x, v.x);
            acc.y = fmaxf(acc.y, v.y);
            acc.z = fmaxf(acc.z, v.z);
            acc.w = fmaxf(acc.w, v.w);
        }
        for (int j = 32; j < count; j += 2) {             // practically never taken
            int jj = j + g; if (jj >= count) jj = count - 1;
            int pid = g_pids[start + jj];
            float4 v = x4[pid * 16 + s];
            acc.x = fmaxf(acc.x, v.x);
            acc.y = fmaxf(acc.y, v.y);
            acc.z = fmaxf(acc.z, v.z);
            acc.w = fmaxf(acc.w, v.w);
        }
        acc.x = fmaxf(acc.x, __shfl_xor_sync(0xffffffffu, acc.x, 16));
        acc.y = fmaxf(acc.y, __shfl_xor_sync(0xffffffffu, acc.y, 16));
        acc.z = fmaxf(acc.z, __shfl_xor_sync(0xffffffffu, acc.z, 16));
        acc.w = fmaxf(acc.w, __shfl_xor_sync(0xffffffffu, acc.w, 16));
    }
    if (lane < 16) out4[warp * 16 + lane] = acc;          // 256B STG.128 row
}

// ---------------------------------------------------------------
extern "C" void kernel_launch(void* const* d_in, const int* in_sizes, int n_in,
                              void* d_out, int out_size) {
    const float* x     = (const float*)d_in[0];
    const int2*  pos   = (const int2*)d_in[1];
    const int*   batch = (const int*)d_in[2];
    float* out = (float*)d_out;
    int n = in_sizes[2];     // number of points

    k_hist   <<<(n + 255) / 256, 256>>>(pos, batch, n);
    k_scan   <<<SCAN_BLOCKS, 1024>>>();
    k_scatter<<<(n + 255) / 256, 256>>>(n);
    k_gather <<<SEGS / 8, 256>>>((const float4*)x, (float4*)out);
}

// round 6
// speedup vs baseline: 4.3817x; 4.3817x over previous
#include <cuda_runtime.h>

#define N_MAX     1048576
#define SEGS      (64 * 4096)   // 262144 segments
#define GRID_DIM  64
#define NUM_CELLS 4096
#define SCAN_BLOCKS 256
#define CPB       32            // cells per gather block
#define STAGE_MAX 512           // staged pids per gather block

// ---- scratch (static device globals; zero-initialized at module load) ----
__device__ int g_idx[N_MAX];          // per-point cell index
__device__ int g_pids[N_MAX];         // point ids sorted by cell
__device__ int g_counts[SEGS];        // points per cell (re-zeroed by k_scan)
__device__ int g_offsets[SEGS];       // exclusive prefix of counts
__device__ int g_cursor[SEGS];        // running write cursor for scatter
__device__ int g_blocksums[SCAN_BLOCKS];
__device__ int g_prefix[SCAN_BLOCKS]; // exclusive scan of block totals
__device__ int g_done;                // arrival counter (reset by k_gather)
__device__ int g_flag;                // publish flag   (reset by k_gather)

// ---------------------------------------------------------------
// pos/batch are int32 (JAX x64 disabled => int64 request materializes int32)
__global__ void k_hist(const int2* __restrict__ pos,
                       const int* __restrict__ batch, int n) {
    int i = blockIdx.x * blockDim.x + threadIdx.x;
    if (i >= n) return;
    int2 p = pos[i];
    int idx = batch[i] * NUM_CELLS
            + (p.x >> 2) * GRID_DIM
            + (p.y >> 2);
    g_idx[i] = idx;
    atomicAdd(&g_counts[idx], 1);
}

// Single-pass scan, single-hop sync: all 256 blocks are co-resident
// (1024 thr -> >=2 blocks/SM on 148 SMs). Each block computes its local scan
// and total; the LAST block to arrive scans the 256 totals and publishes
// g_prefix + g_flag; every block then adds its base. One flag hop total.
__global__ void k_scan() {
    int bid  = blockIdx.x;
    int i    = bid * 1024 + threadIdx.x;
    int lane = threadIdx.x & 31;
    int wid  = threadIdx.x >> 5;

    int v = g_counts[i];
    g_counts[i] = 0;                       // consumed; reset for next replay

    int incl = v;
    #pragma unroll
    for (int d = 1; d < 32; d <<= 1) {
        int u = __shfl_up_sync(0xffffffffu, incl, d);
        if (lane >= d) incl += u;
    }
    __shared__ int ws[32];
    __shared__ int wexcl[32];
    __shared__ int s_last;
    __shared__ int s_base;
    if (lane == 31) ws[wid] = incl;
    __syncthreads();
    if (wid == 0) {
        int w  = ws[lane];
        int wi = w;
        #pragma unroll
        for (int d = 1; d < 32; d <<= 1) {
            int u = __shfl_up_sync(0xffffffffu, wi, d);
            if (lane >= d) wi += u;
        }
        wexcl[lane] = wi - w;
        if (lane == 31) {
            g_blocksums[bid] = wi;         // block total
            __threadfence();
            int t = atomicAdd(&g_done, 1);
            s_last = (t == SCAN_BLOCKS - 1);
        }
    }
    __syncthreads();

    if (s_last) {                          // block-uniform branch
        // exclusive scan of 256 block totals by threads 0..255
        __shared__ int ws2[8];
        int t = threadIdx.x;
        int bv = 0, bi = 0;
        if (t < SCAN_BLOCKS) {
            bv = g_blocksums[t];
            bi = bv;
            #pragma unroll
            for (int d = 1; d < 32; d <<= 1) {
                int u = __shfl_up_sync(0xffffffffu, bi, d);
                if ((t & 31) >= d) bi += u;
            }
            if ((t & 31) == 31) ws2[t >> 5] = bi;
        }
        __syncthreads();
        if (t < SCAN_BLOCKS) {
            int add = 0;
            #pragma unroll
            for (int wq = 0; wq < 8; wq++)
                if (wq < (t >> 5)) add += ws2[wq];
            g_prefix[t] = bi - bv + add;   // exclusive base for block t
        }
        __syncthreads();
        if (t == 0) {
            __threadfence();
            atomicExch(&g_flag, 1);        // publish
        }
    }

    // all blocks: wait for publish (single hop), then finalize
    if (threadIdx.x == 0) {
        while (atomicAdd(&g_flag, 0) == 0) { __nanosleep(100); }
        __threadfence();
        s_base = g_prefix[bid];
    }
    __syncthreads();

    int o = incl - v + wexcl[wid] + s_base;
    g_offsets[i] = o;
    g_cursor[i]  = o;
}

__global__ void k_scatter(int n) {
    int i = blockIdx.x * blockDim.x + threadIdx.x;
    if (i >= n) return;
    int idx = g_idx[i];
    int p = atomicAdd(&g_cursor[idx], 1);
    g_pids[p] = i;
}

// Gather: block = 32 contiguous cells. Meta (offset/cursor) loaded coalesced
// into smem; the cells' pids occupy a CONTIGUOUS g_pids range -> staged into
// smem with coalesced loads. Row loads then depend only on smem, so each warp
// streams ~8 independent 512B row loads (high MLP). Overflow (>512 pids per
// 32 cells; ~never under Poisson(3.8)/cell) falls back to global pid reads.
__global__ void k_gather(const float4* __restrict__ x4, float4* __restrict__ out4) {
    if (blockIdx.x == 0 && threadIdx.x == 0) { g_done = 0; g_flag = 0; }

    __shared__ int s_off[CPB];
    __shared__ int s_cnt[CPB];
    __shared__ int s_pid[STAGE_MAX];

    int tid   = threadIdx.x;
    int cbase = blockIdx.x * CPB;

    if (tid < CPB) {
        int off = g_offsets[cbase + tid];
        s_off[tid] = off;
        s_cnt[tid] = g_cursor[cbase + tid] - off;
    }
    __syncthreads();

    int base0 = s_off[0];
    int total = s_off[CPB - 1] + s_cnt[CPB - 1] - base0;
    int stage = total < STAGE_MAX ? total : STAGE_MAX;
    for (int i = tid; i < stage; i += 256)
        s_pid[i] = g_pids[base0 + i];
    __syncthreads();

    int warp = tid >> 5;
    int lane = tid & 31;
    int g    = lane >> 4;       // point-pair group (0/1)
    int s    = lane & 15;       // float4 column within 64-ch row

    const float ninf = __int_as_float(0xff800000);

    #pragma unroll
    for (int ci = 0; ci < 4; ci++) {        // 8 warps x 4 cells = 32
        int c     = warp * 4 + ci;
        int count = s_cnt[c];
        int start = s_off[c];
        int ls    = start - base0;

        float4 acc = make_float4(0.f, 0.f, 0.f, 0.f);
        if (count > 0) {
            acc = make_float4(ninf, ninf, ninf, ninf);
            bool insm = (ls + count) <= stage;
            for (int j = 0; j < count; j += 2) {
                int jj = j + g; if (jj >= count) jj = count - 1;  // odd tail dup
                int pid = insm ? s_pid[ls + jj] : g_pids[start + jj];
                float4 v = x4[pid * 16 + s];          // 256B row, 2 points/iter
                acc.x = fmaxf(acc.x, v.x);
                acc.y = fmaxf(acc.y, v.y);
                acc.z = fmaxf(acc.z, v.z);
                acc.w = fmaxf(acc.w, v.w);
            }
            acc.x = fmaxf(acc.x, __shfl_xor_sync(0xffffffffu, acc.x, 16));
            acc.y = fmaxf(acc.y, __shfl_xor_sync(0xffffffffu, acc.y, 16));
            acc.z = fmaxf(acc.z, __shfl_xor_sync(0xffffffffu, acc.z, 16));
            acc.w = fmaxf(acc.w, __shfl_xor_sync(0xffffffffu, acc.w, 16));
        }
        if (lane < 16) out4[(cbase + c) * 16 + lane] = acc;   // 256B STG.128
    }
}

// ---------------------------------------------------------------
extern "C" void kernel_launch(void* const* d_in, const int* in_sizes, int n_in,
                              void* d_out, int out_size) {
    const float* x     = (const float*)d_in[0];
    const int2*  pos   = (const int2*)d_in[1];
    const int*   batch = (const int*)d_in[2];
    float* out = (float*)d_out;
    int n = in_sizes[2];     // number of points

    k_hist   <<<(n + 255) / 256, 256>>>(pos, batch, n);
    k_scan   <<<SCAN_BLOCKS, 1024>>>();
    k_scatter<<<(n + 255) / 256, 256>>>(n);
    k_gather <<<SEGS / CPB, 256>>>((const float4*)x, (float4*)out);
}